// round 11
// baseline (speedup 1.0000x reference)
#include <cuda_runtime.h>
#include <cuda_fp16.h>
#include <cuda_bf16.h>
#include <cstdint>

// ---------------------------------------------------------------------------
// Gaussian rasterizer, R11:
//  A: project all 512 gaussians (4 CTAs x 128) -> device globals, then
//     cudaTriggerProgrammaticLaunchCompletion.
//  B: launched with programmatic stream serialization (PDL) so its launch
//     overlaps A; cudaGridDependencySynchronize before reading A's output.
//     Mask test via center/half-extent + one half2 compare (exact fp16).
// ---------------------------------------------------------------------------

#define NG    512
#define IMG   256
#define TW    16
#define TH    16
#define NT    256
#define NWARP (NT/32)

__device__ float4 g_rec[NG][3];
__device__ uint2  g_bb[NG];
__device__ float  g_z[NG];

__device__ __forceinline__ float ex2(float x) {
    float y;
    asm("ex2.approx.ftz.f32 %0, %1;" : "=f"(y) : "f"(x));
    return y;
}

// ------------------------------ kernel A -----------------------------------
__global__ __launch_bounds__(128)
void gs_project(const float* __restrict__ pos,
                const float* __restrict__ cov3d,
                const float* __restrict__ opac,
                const float* __restrict__ cols,
                const float* __restrict__ Km,
                const float* __restrict__ Rm,
                const float* __restrict__ tv)
{
    const int g = blockIdx.x * 128 + threadIdx.x;

    const float r00 = Rm[0], r01 = Rm[1], r02 = Rm[2];
    const float r10 = Rm[3], r11 = Rm[4], r12 = Rm[5];
    const float r20 = Rm[6], r21 = Rm[7], r22 = Rm[8];
    const float fx  = Km[0], fy = Km[4];

    const float p0 = pos[3*g+0], p1 = pos[3*g+1], p2 = pos[3*g+2];

    const float cam0 = r00*p0 + r01*p1 + r02*p2 + tv[0];
    const float cam1 = r10*p0 + r11*p1 + r12*p2 + tv[1];
    const float cam2 = r20*p0 + r21*p1 + r22*p2 + tv[2];

    const float pr0 = Km[0]*cam0 + Km[1]*cam1 + Km[2]*cam2;
    const float pr1 = Km[3]*cam0 + Km[4]*cam1 + Km[5]*cam2;
    const float pr2 = Km[6]*cam0 + Km[7]*cam1 + Km[8]*cam2;
    const float rz = 1.0f / pr2;
    const float mx = pr0 * rz;
    const float my = pr1 * rz;

    const float z   = cam2;
    const float iz  = 1.0f / z;
    const float jx0 = fx * iz;
    const float jx2 = -fx * cam0 * iz * iz;
    const float jy1 = fy * iz;
    const float jy2 = -fy * cam1 * iz * iz;

    // P = J * R  (2x3)
    const float P00 = jx0*r00 + jx2*r20;
    const float P01 = jx0*r01 + jx2*r21;
    const float P02 = jx0*r02 + jx2*r22;
    const float P10 = jy1*r10 + jy2*r20;
    const float P11 = jy1*r11 + jy2*r21;
    const float P12 = jy1*r12 + jy2*r22;

    // symmetric C
    const float c00 = cov3d[9*g+0];
    const float c01 = cov3d[9*g+1];
    const float c02 = cov3d[9*g+2];
    const float c11 = cov3d[9*g+4];
    const float c12 = cov3d[9*g+5];
    const float c22 = cov3d[9*g+8];

    const float t00 = c00*P00 + c01*P01 + c02*P02;
    const float t01 = c01*P00 + c11*P01 + c12*P02;
    const float t02 = c02*P00 + c12*P01 + c22*P02;
    const float t10 = c00*P10 + c01*P11 + c02*P12;
    const float t11 = c01*P10 + c11*P11 + c12*P12;
    const float t12 = c02*P10 + c12*P11 + c22*P12;

    const float a = P00*t00 + P01*t01 + P02*t02 + 0.3f;
    const float b = P10*t00 + P11*t01 + P12*t02;
    const float c = P10*t10 + P11*t11 + P12*t12 + 0.3f;

    const float det  = fmaxf(a*c - b*b, 1e-8f);
    const float idet = 1.0f / det;
    // exp2 prescale: exp(-0.5*m) = exp2(-0.72134752*m)
    const float e00 = -0.72134752f * c * idet;
    const float e01 =  1.44269504f * b * idet;
    const float e11 = -0.72134752f * a * idet;

    const float hd = (a - c) * 0.5f;
    const float max_eig = (a + c)*0.5f + sqrtf(fmaxf(hd*hd + b*b, 1e-8f));
    const float radius = 3.0f * sqrtf(max_eig);

    const float x_min = fmaxf(0.0f,       truncf(mx - radius));
    const float x_max = fminf((float)IMG, truncf(mx + radius) + 1.0f);
    const float y_min = fmaxf(0.0f,       truncf(my - radius));
    const float y_max = fminf((float)IMG, truncf(my + radius) + 1.0f);

    const float bias = __log2f(opac[g]);

    // center/half-extent form: |px-bcx|<bhx  <=>  x_min <= px <= x_max-1
    const float bcx = (x_min + x_max - 1.0f) * 0.5f;
    const float bcy = (y_min + y_max - 1.0f) * 0.5f;
    const float bhx = (x_max - x_min) * 0.5f;   // multiple of 0.5, exact fp16
    const float bhy = (y_max - y_min) * 0.5f;
    const __half2 h2 = __floats2half2_rn(bhx, bhy);
    const unsigned h2bits = *reinterpret_cast<const unsigned*>(&h2);

    g_rec[g][0] = make_float4(mx, my, e00, e01);
    g_rec[g][1] = make_float4(e11, bias, bcx, bcy);
    g_rec[g][2] = make_float4(cols[3*g+0], cols[3*g+1], cols[3*g+2],
                              __uint_as_float(h2bits));
    g_bb[g] = make_uint2((unsigned)x_min | ((unsigned)x_max << 16),
                         (unsigned)y_min | ((unsigned)y_max << 16));
    g_z[g]  = z;

    cudaTriggerProgrammaticLaunchCompletion();
}

// ------------------------------ kernel B -----------------------------------
__global__ __launch_bounds__(NT)
void gs_raster(float* __restrict__ out)
{
    __shared__ float4             rec[NG + 4][3];  // ~24.2 KB
    __shared__ unsigned long long skey[NG];        // 4 KB
    __shared__ int                warpTotals[NWARP];

    const int tid  = threadIdx.x;
    const int lane = tid & 31;
    const int wid  = tid >> 5;

    const int tileX = blockIdx.x * TW;
    const int tileY = blockIdx.y * TH;

    // PDL: wait for gs_project's stores to be visible
    cudaGridDependencySynchronize();

    // ---------------- phase 1: cull 2 gaussians/thread ----------------
    bool  flg[2];
    unsigned long long key[2];
    float4 R0[2], R1[2], R2[2];

    #pragma unroll
    for (int s = 0; s < 2; s++) {
        const int g = tid + s * NT;
        const uint2 bb = g_bb[g];                       // coalesced LDG.64
        const int x0 = (int)(bb.x & 0xffffu), x1 = (int)(bb.x >> 16);
        const int y0 = (int)(bb.y & 0xffffu), y1 = (int)(bb.y >> 16);
        flg[s] = (x0 < tileX + TW) & (x1 > tileX) &
                 (y0 < tileY + TH) & (y1 > tileY);
        const float z = g_z[g];                         // coalesced LDG.32
        key[s] = ((unsigned long long)__float_as_uint(z) << 16)
               | (unsigned long long)g;
        if (flg[s]) {                                   // L2 fetch, overlaps rank
            R0[s] = g_rec[g][0];
            R1[s] = g_rec[g][1];
            R2[s] = g_rec[g][2];
        }
    }

    // ---------------- phase 2: compaction slots ----------------
    const unsigned m0 = __ballot_sync(0xffffffffu, flg[0]);
    const unsigned m1 = __ballot_sync(0xffffffffu, flg[1]);
    if (lane == 0) warpTotals[wid] = __popc(m0) | (__popc(m1) << 16);
    __syncthreads();

    int prefix = 0, total = 0;
    #pragma unroll
    for (int w = 0; w < NWARP; w++) {
        const int t = warpTotals[w];
        if (w < wid) prefix += t;
        total += t;
    }
    const int count0 = total & 0xffff;
    const int count  = count0 + (total >> 16);
    const unsigned lm = (1u << lane) - 1u;
    const int pos0 = (prefix & 0xffff) + __popc(m0 & lm);
    const int pos1 = count0 + (prefix >> 16) + __popc(m1 & lm);

    if (flg[0]) skey[pos0] = key[0];
    if (flg[1]) skey[pos1] = key[1];
    __syncthreads();

    // ---------------- phase 3: rank over survivors only ----------------
    int rank0 = 0, rank1 = 0;
    if (flg[0] | flg[1]) {
        for (int j = 0; j < count; j++) {
            const unsigned long long kj = skey[j];
            rank0 += (kj < key[0]);
            rank1 += (kj < key[1]);
        }
    }
    // scatter records into depth order (rec distinct from skey: no barrier)
    if (flg[0]) { rec[rank0][0] = R0[0]; rec[rank0][1] = R1[0]; rec[rank0][2] = R2[0]; }
    if (flg[1]) { rec[rank1][0] = R0[1]; rec[rank1][1] = R1[1]; rec[rank1][2] = R2[1]; }

    const int countPad = (count + 3) & ~3;
    for (int t2 = count + tid; t2 < countPad; t2 += NT) {
        rec[t2][0] = make_float4(0.f, 0.f, 0.f, 0.f);
        rec[t2][1] = make_float4(0.f, 0.f, 0.f, 0.f);
        rec[t2][2] = make_float4(0.f, 0.f, 0.f, 0.f);   // h2=0 -> mask false
    }
    __syncthreads();

    // ---------------- phase 4: composite, 1 px/thread ----------------
    const int pxi = tileX + (tid & (TW - 1));
    const int pyi = tileY + (tid >> 4);
    const float pxf = (float)pxi;
    const float pyf = (float)pyi;

    float T = 1.0f, rr = 0.0f, gg = 0.0f, bb = 0.0f;
    for (int base = 0; base < countPad; base += 4) {
        float4 q0[4], q1[4], q2[4];
        #pragma unroll
        for (int i = 0; i < 4; i++) {
            q0[i] = rec[base+i][0];
            q1[i] = rec[base+i][1];
            q2[i] = rec[base+i][2];
        }
        float gs[4];
        #pragma unroll
        for (int i = 0; i < 4; i++) {
            // mask: |px-bcx|<bhx && |py-bcy|<bhy via one half2 compare (exact)
            const float dxc = pxf - q1[i].z;
            const float dyc = pyf - q1[i].w;
            const unsigned hb = __float_as_uint(q2[i].w);
            const __half2 h2 = *reinterpret_cast<const __half2*>(&hb);
            const __half2 d2 = __habs2(__floats2half2_rn(dxc, dyc));
            const bool inb = __hbgt2(h2, d2);

            const float dx = pxf - q0[i].x;
            const float dy = pyf - q0[i].y;
            const float u  = fmaf(q1[i].x * dy, dy, q1[i].y);   // e11*dy^2 + bias
            const float pl = fmaf(q0[i].w, dy, q0[i].z * dx);   // e01*dy + e00*dx
            const float e  = fmaf(pl, dx, u);
            gs[i] = inb ? ex2(e) : 0.0f;                        // alpha
        }
        #pragma unroll
        for (int i = 0; i < 4; i++) {
            const float tg = T * gs[i];
            rr = fmaf(tg, q2[i].x, rr);
            gg = fmaf(tg, q2[i].y, gg);
            bb = fmaf(tg, q2[i].z, bb);
            T  = T - tg;
        }
        if (T < 1e-5f) break;
    }

    const int idx = (pyi * IMG + pxi) * 3;
    out[idx + 0] = rr;
    out[idx + 1] = gg;
    out[idx + 2] = bb;
}

extern "C" void kernel_launch(void* const* d_in, const int* in_sizes, int n_in,
                              void* d_out, int out_size)
{
    const float* pos   = (const float*)d_in[0];  // (512,3)
    const float* cov3d = (const float*)d_in[1];  // (512,3,3)
    const float* opac  = (const float*)d_in[2];  // (512,1)
    const float* cols  = (const float*)d_in[3];  // (512,3)
    const float* Km    = (const float*)d_in[4];  // (3,3)
    const float* Rm    = (const float*)d_in[5];  // (3,3)
    const float* tv    = (const float*)d_in[6];  // (3,)
    float* out = (float*)d_out;                  // (256,256,3)

    gs_project<<<4, 128>>>(pos, cov3d, opac, cols, Km, Rm, tv);

    // PDL launch of the raster kernel: overlaps its launch with gs_project.
    cudaLaunchConfig_t cfg = {};
    cfg.gridDim  = dim3(IMG/TW, IMG/TH);
    cfg.blockDim = dim3(NT);
    cfg.dynamicSmemBytes = 0;
    cfg.stream = 0;
    cudaLaunchAttribute at[1];
    at[0].id = cudaLaunchAttributeProgrammaticStreamSerialization;
    at[0].val.programmaticStreamSerializationAllowed = 1;
    cfg.attrs = at;
    cfg.numAttrs = 1;
    cudaLaunchKernelEx(&cfg, gs_raster, (float*)d_out);
}

// round 12
// speedup vs baseline: 1.0463x; 1.0463x over previous
#include <cuda_runtime.h>
#include <cuda_bf16.h>
#include <cstdint>

// ---------------------------------------------------------------------------
// Gaussian rasterizer, R12 = R10 base (two plain kernels) plus:
//  - vsub2 SIMD u16 in-box mask (4 ALU vs ~10), empty boxes canonicalized
//  - fused cull word (bbox lo, bbox hi-1, z bits) -> single LDG.128
// ---------------------------------------------------------------------------

#define NG    512
#define IMG   256
#define TW    16
#define TH    16
#define NT    256
#define NWARP (NT/32)

__device__ float4 g_rec[NG][3];
__device__ uint4  g_cull[NG];

__device__ __forceinline__ float ex2(float x) {
    float y;
    asm("ex2.approx.ftz.f32 %0, %1;" : "=f"(y) : "f"(x));
    return y;
}

// ------------------------------ kernel A -----------------------------------
__global__ __launch_bounds__(128)
void gs_project(const float* __restrict__ pos,
                const float* __restrict__ cov3d,
                const float* __restrict__ opac,
                const float* __restrict__ cols,
                const float* __restrict__ Km,
                const float* __restrict__ Rm,
                const float* __restrict__ tv)
{
    const int g = blockIdx.x * 128 + threadIdx.x;

    const float r00 = Rm[0], r01 = Rm[1], r02 = Rm[2];
    const float r10 = Rm[3], r11 = Rm[4], r12 = Rm[5];
    const float r20 = Rm[6], r21 = Rm[7], r22 = Rm[8];
    const float fx  = Km[0], fy = Km[4];

    const float p0 = pos[3*g+0], p1 = pos[3*g+1], p2 = pos[3*g+2];

    const float cam0 = r00*p0 + r01*p1 + r02*p2 + tv[0];
    const float cam1 = r10*p0 + r11*p1 + r12*p2 + tv[1];
    const float cam2 = r20*p0 + r21*p1 + r22*p2 + tv[2];

    const float pr0 = Km[0]*cam0 + Km[1]*cam1 + Km[2]*cam2;
    const float pr1 = Km[3]*cam0 + Km[4]*cam1 + Km[5]*cam2;
    const float pr2 = Km[6]*cam0 + Km[7]*cam1 + Km[8]*cam2;
    const float rz = 1.0f / pr2;
    const float mx = pr0 * rz;
    const float my = pr1 * rz;

    const float z   = cam2;
    const float iz  = 1.0f / z;
    const float jx0 = fx * iz;
    const float jx2 = -fx * cam0 * iz * iz;
    const float jy1 = fy * iz;
    const float jy2 = -fy * cam1 * iz * iz;

    // P = J * R  (2x3)
    const float P00 = jx0*r00 + jx2*r20;
    const float P01 = jx0*r01 + jx2*r21;
    const float P02 = jx0*r02 + jx2*r22;
    const float P10 = jy1*r10 + jy2*r20;
    const float P11 = jy1*r11 + jy2*r21;
    const float P12 = jy1*r12 + jy2*r22;

    // symmetric C
    const float c00 = cov3d[9*g+0];
    const float c01 = cov3d[9*g+1];
    const float c02 = cov3d[9*g+2];
    const float c11 = cov3d[9*g+4];
    const float c12 = cov3d[9*g+5];
    const float c22 = cov3d[9*g+8];

    const float t00 = c00*P00 + c01*P01 + c02*P02;
    const float t01 = c01*P00 + c11*P01 + c12*P02;
    const float t02 = c02*P00 + c12*P01 + c22*P02;
    const float t10 = c00*P10 + c01*P11 + c02*P12;
    const float t11 = c01*P10 + c11*P11 + c12*P12;
    const float t12 = c02*P10 + c12*P11 + c22*P12;

    const float a = P00*t00 + P01*t01 + P02*t02 + 0.3f;
    const float b = P10*t00 + P11*t01 + P12*t02;
    const float c = P10*t10 + P11*t11 + P12*t12 + 0.3f;

    const float det  = fmaxf(a*c - b*b, 1e-8f);
    const float idet = 1.0f / det;
    // exp2 prescale: exp(-0.5*m) = exp2(-0.72134752*m)
    const float e00 = -0.72134752f * c * idet;
    const float e01 =  1.44269504f * b * idet;
    const float e11 = -0.72134752f * a * idet;

    const float hd = (a - c) * 0.5f;
    const float max_eig = (a + c)*0.5f + sqrtf(fmaxf(hd*hd + b*b, 1e-8f));
    const float radius = 3.0f * sqrtf(max_eig);

    const float x_min = fmaxf(0.0f,       truncf(mx - radius));
    const float x_max = fminf((float)IMG, truncf(mx + radius) + 1.0f);
    const float y_min = fmaxf(0.0f,       truncf(my - radius));
    const float y_max = fminf((float)IMG, truncf(my + radius) + 1.0f);

    const float bias = __log2f(opac[g]);

    // u16-packed cull/mask words. Empty boxes (offscreen) canonicalized so
    // both the tile cull and the pixel mask reject them.
    unsigned lo, hm1;
    if (x_max <= x_min || y_max <= y_min) {
        lo  = 0x7FFF7FFFu;   // x0=y0=32767 -> always culled / masked out
        hm1 = 0u;
    } else {
        const unsigned x0  = (unsigned)x_min;
        const unsigned y0  = (unsigned)y_min;
        const unsigned x1m = (unsigned)(x_max - 1.0f);
        const unsigned y1m = (unsigned)(y_max - 1.0f);
        lo  = x0  | (y0  << 16);
        hm1 = x1m | (y1m << 16);
    }

    g_rec[g][0] = make_float4(mx, my, e00, e01);
    g_rec[g][1] = make_float4(e11, bias,
                              __uint_as_float(lo), __uint_as_float(hm1));
    g_rec[g][2] = make_float4(cols[3*g+0], cols[3*g+1], cols[3*g+2], 0.f);
    g_cull[g] = make_uint4(lo, hm1, __float_as_uint(z), 0u);
}

// ------------------------------ kernel B -----------------------------------
__global__ __launch_bounds__(NT)
void gs_raster(float* __restrict__ out)
{
    __shared__ float4             rec[NG + 4][3];  // ~24.2 KB
    __shared__ unsigned long long skey[NG];        // 4 KB
    __shared__ int                warpTotals[NWARP];

    const int tid  = threadIdx.x;
    const int lane = tid & 31;
    const int wid  = tid >> 5;

    const int tileX = blockIdx.x * TW;
    const int tileY = blockIdx.y * TH;

    // ---------------- phase 1: cull 2 gaussians/thread ----------------
    bool  flg[2];
    unsigned long long key[2];
    float4 R0[2], R1[2], R2[2];

    #pragma unroll
    for (int s = 0; s < 2; s++) {
        const int g = tid + s * NT;
        const uint4 cw = g_cull[g];                     // coalesced LDG.128
        const int x0  = (int)(cw.x & 0xffffu), y0  = (int)(cw.x >> 16);
        const int x1m = (int)(cw.y & 0xffffu), y1m = (int)(cw.y >> 16);
        flg[s] = (x0 < tileX + TW) & (x1m >= tileX) &
                 (y0 < tileY + TH) & (y1m >= tileY);
        key[s] = ((unsigned long long)cw.z << 16) | (unsigned long long)g;
        if (flg[s]) {                                   // L2 fetch, overlaps rank
            R0[s] = g_rec[g][0];
            R1[s] = g_rec[g][1];
            R2[s] = g_rec[g][2];
        }
    }

    // ---------------- phase 2: compaction slots ----------------
    const unsigned m0 = __ballot_sync(0xffffffffu, flg[0]);
    const unsigned m1 = __ballot_sync(0xffffffffu, flg[1]);
    if (lane == 0) warpTotals[wid] = __popc(m0) | (__popc(m1) << 16);
    __syncthreads();

    int prefix = 0, total = 0;
    #pragma unroll
    for (int w = 0; w < NWARP; w++) {
        const int t = warpTotals[w];
        if (w < wid) prefix += t;
        total += t;
    }
    const int count0 = total & 0xffff;
    const int count  = count0 + (total >> 16);
    const unsigned lm = (1u << lane) - 1u;
    const int pos0 = (prefix & 0xffff) + __popc(m0 & lm);
    const int pos1 = count0 + (prefix >> 16) + __popc(m1 & lm);

    if (flg[0]) skey[pos0] = key[0];
    if (flg[1]) skey[pos1] = key[1];
    __syncthreads();

    // ---------------- phase 3: rank over survivors only ----------------
    int rank0 = 0, rank1 = 0;
    if (flg[0] | flg[1]) {
        for (int j = 0; j < count; j++) {
            const unsigned long long kj = skey[j];
            rank0 += (kj < key[0]);
            rank1 += (kj < key[1]);
        }
    }
    // scatter records into depth order (rec distinct from skey: no barrier)
    if (flg[0]) { rec[rank0][0] = R0[0]; rec[rank0][1] = R1[0]; rec[rank0][2] = R2[0]; }
    if (flg[1]) { rec[rank1][0] = R0[1]; rec[rank1][1] = R1[1]; rec[rank1][2] = R2[1]; }

    const int countPad = (count + 3) & ~3;
    for (int t2 = count + tid; t2 < countPad; t2 += NT) {
        rec[t2][0] = make_float4(0.f, 0.f, 0.f, 0.f);
        rec[t2][1] = make_float4(0.f, 0.f,
                                 __uint_as_float(0x7FFF7FFFu), 0.f);
        rec[t2][2] = make_float4(0.f, 0.f, 0.f, 0.f);
    }
    __syncthreads();

    // ---------------- phase 4: composite, 1 px/thread ----------------
    const int pxi = tileX + (tid & (TW - 1));
    const int pyi = tileY + (tid >> 4);
    const float pxf = (float)pxi;
    const float pyf = (float)pyi;
    const unsigned pxy = (unsigned)pxi | ((unsigned)pyi << 16);

    float T = 1.0f, rr = 0.0f, gg = 0.0f, bb = 0.0f;
    for (int base = 0; base < countPad; base += 4) {
        float4 q0[4], q1[4], q2[4];
        #pragma unroll
        for (int i = 0; i < 4; i++) {
            q0[i] = rec[base+i][0];
            q1[i] = rec[base+i][1];
            q2[i] = rec[base+i][2];
        }
        float gs[4];
        #pragma unroll
        for (int i = 0; i < 4; i++) {
            // SIMD u16 in-box test: inside iff no halfword of (pxy-lo) or
            // (hm1-pxy) underflows (sign bits clear).
            const unsigned lo  = __float_as_uint(q1[i].z);
            const unsigned hm1 = __float_as_uint(q1[i].w);
            const unsigned ua  = __vsub2(pxy, lo);
            const unsigned ub  = __vsub2(hm1, pxy);
            const bool inb = ((ua | ub) & 0x80008000u) == 0u;

            const float dx = pxf - q0[i].x;
            const float dy = pyf - q0[i].y;
            const float u  = fmaf(q1[i].x * dy, dy, q1[i].y);   // e11*dy^2 + bias
            const float pl = fmaf(q0[i].w, dy, q0[i].z * dx);   // e01*dy + e00*dx
            const float e  = fmaf(pl, dx, u);
            gs[i] = inb ? ex2(e) : 0.0f;                        // alpha
        }
        #pragma unroll
        for (int i = 0; i < 4; i++) {
            const float tg = T * gs[i];
            rr = fmaf(tg, q2[i].x, rr);
            gg = fmaf(tg, q2[i].y, gg);
            bb = fmaf(tg, q2[i].z, bb);
            T  = T - tg;
        }
        if (T < 1e-5f) break;
    }

    const int idx = (pyi * IMG + pxi) * 3;
    out[idx + 0] = rr;
    out[idx + 1] = gg;
    out[idx + 2] = bb;
}

extern "C" void kernel_launch(void* const* d_in, const int* in_sizes, int n_in,
                              void* d_out, int out_size)
{
    const float* pos   = (const float*)d_in[0];  // (512,3)
    const float* cov3d = (const float*)d_in[1];  // (512,3,3)
    const float* opac  = (const float*)d_in[2];  // (512,1)
    const float* cols  = (const float*)d_in[3];  // (512,3)
    const float* Km    = (const float*)d_in[4];  // (3,3)
    const float* Rm    = (const float*)d_in[5];  // (3,3)
    const float* tv    = (const float*)d_in[6];  // (3,)
    float* out = (float*)d_out;                  // (256,256,3)

    gs_project<<<4, 128>>>(pos, cov3d, opac, cols, Km, Rm, tv);
    gs_raster<<<dim3(IMG/TW, IMG/TH), NT>>>(out);
}